// round 15
// baseline (speedup 1.0000x reference)
#include <cuda_runtime.h>
#include <cuda_fp16.h>
#include <cfloat>
#include <math.h>
#include <stdint.h>

// Problem constants
#define BB 4
#define SS 2048
#define DD 1024
#define HH 16
#define HD 64
#define MM (BB*SS)   // 8192

// ---------------------------------------------------------------------------
// Scratch (static device arrays; allocation-free per harness rules)
// ---------------------------------------------------------------------------
__device__ float g_qp[MM*DD];                       // Wo-GEMM fp32 output
__device__ __half g_q16[MM*DD], g_k16[MM*DD], g_v16[MM*DD];   // rounded inputs
__device__ __half g_qp16[MM*DD];                    // Q proj (scaled 0.125*log2e)
__device__ __half g_kp16[MM*DD];                    // K proj
__device__ __half g_vp16[MM*DD];                    // V proj
__device__ __half g_ao16[MM*DD];                    // attention out
__device__ __half g_w0[DD*DD], g_w1[DD*DD], g_w2[DD*DD], g_w3[DD*DD];
__device__ int g_cidx[BB*SS];
__device__ int g_pcnt[BB*SS];

// ---------------------------------------------------------------------------
// Common helpers
// ---------------------------------------------------------------------------
__device__ __forceinline__ uint32_t smem_u32(const void* p) {
    uint32_t a;
    asm("{ .reg .u64 t; cvta.to.shared.u64 t, %1; cvt.u32.u64 %0, t; }"
        : "=r"(a) : "l"(p));
    return a;
}
__device__ __forceinline__ void cpasync16(uint32_t dst, const void* src) {
    asm volatile("cp.async.cg.shared.global [%0], [%1], 16;" :: "r"(dst), "l"(src));
}
#define CP_COMMIT() asm volatile("cp.async.commit_group;" ::: "memory")
#define CP_WAIT0()  asm volatile("cp.async.wait_group 0;" ::: "memory")
#define CP_WAIT1()  asm volatile("cp.async.wait_group 1;" ::: "memory")

#define MMAH(d, a, b0v, b1v) \
    asm volatile("mma.sync.aligned.m16n8k16.row.col.f32.f16.f16.f32 " \
        "{%0,%1,%2,%3}, {%4,%5,%6,%7}, {%8,%9}, {%0,%1,%2,%3};\n" \
        : "+f"((d)[0]), "+f"((d)[1]), "+f"((d)[2]), "+f"((d)[3]) \
        : "r"((a)[0]), "r"((a)[1]), "r"((a)[2]), "r"((a)[3]), \
          "r"(b0v), "r"(b1v))

#define LDSM4(r, addr) \
    asm volatile("ldmatrix.sync.aligned.m8n8.x4.shared.b16 {%0,%1,%2,%3}, [%4];" \
        : "=r"((r)[0]), "=r"((r)[1]), "=r"((r)[2]), "=r"((r)[3]) : "r"(addr))
#define LDSM4T(r, addr) \
    asm volatile("ldmatrix.sync.aligned.m8n8.x4.trans.shared.b16 {%0,%1,%2,%3}, [%4];" \
        : "=r"((r)[0]), "=r"((r)[1]), "=r"((r)[2]), "=r"((r)[3]) : "r"(addr))

__device__ __forceinline__ uint32_t pack2h(float a, float b) {
    __half2 p = __floats2half2_rn(a, b);
    return *(uint32_t*)&p;
}
__device__ __forceinline__ float ex2f(float x) {
    float y;
    asm("ex2.approx.f32 %0, %1;" : "=f"(y) : "f"(x));
    return y;
}

// ---------------------------------------------------------------------------
// Fused rounding passes
// ---------------------------------------------------------------------------
__global__ __launch_bounds__(256) void round16_act(
    const float* __restrict__ q, const float* __restrict__ k,
    const float* __restrict__ v,
    __half* __restrict__ q16, __half* __restrict__ k16,
    __half* __restrict__ v16, int n4)
{
    int i = blockIdx.x * blockDim.x + threadIdx.x;
    if (i >= n4) return;
    int z = blockIdx.y;
    const float* src = z == 0 ? q : z == 1 ? k : v;
    __half* out = z == 0 ? q16 : z == 1 ? k16 : v16;
    float4 val = ((const float4*)src)[i];
    uint2 o = {pack2h(val.x, val.y), pack2h(val.z, val.w)};
    ((uint2*)out)[i] = o;
}

__global__ __launch_bounds__(256) void round16_w(
    const float* __restrict__ Wq, const float* __restrict__ Wk,
    const float* __restrict__ Wv, const float* __restrict__ Wo,
    __half* __restrict__ w0, __half* __restrict__ w1,
    __half* __restrict__ w2, __half* __restrict__ w3, int n4)
{
    int i = blockIdx.x * blockDim.x + threadIdx.x;
    if (i >= n4) return;
    int z = blockIdx.y;
    const float* src = z == 0 ? Wq : z == 1 ? Wk : z == 2 ? Wv : Wo;
    __half* out = z == 0 ? w0 : z == 1 ? w1 : z == 2 ? w2 : w3;
    float4 val = ((const float4*)src)[i];
    uint2 o = {pack2h(val.x, val.y), pack2h(val.z, val.w)};
    ((uint2*)out)[i] = o;
}

// ---------------------------------------------------------------------------
// fp16 GEMM core: 3-stage cp.async ring, ONE __syncthreads per K-slice.
// 128x128 block, BK=32, 256 threads.
// ---------------------------------------------------------------------------
#define NSLC 32
#define ROWB 80
#define MATB (128*ROWB)
#define STGB (2*MATB)          // A | W per stage (20480 B)
#define GEMM_SMEM (3*STGB)     // 61440

__device__ __forceinline__ void g_load_stage(
    uint32_t sb, int slot, int c, int bm, int bn, int tid,
    const __half* __restrict__ A16, const __half* __restrict__ W16)
{
    const int r = tid >> 1;
    const int ho = (tid & 1) * 16;
    const uint32_t dst = sb + slot * STGB + (uint32_t)r * ROWB + ho * 2;
    const size_t ga = (size_t)(bm + r) * DD + c * 32 + ho;
    const size_t gw = (size_t)(bn + r) * DD + c * 32 + ho;
    cpasync16(dst,        A16 + ga);   cpasync16(dst + 16,        A16 + ga + 8);
    cpasync16(dst + MATB, W16 + gw);   cpasync16(dst + MATB + 16, W16 + gw + 8);
    CP_COMMIT();
}

__device__ __forceinline__ void gemm_core(
    uint32_t sb, int bm, int bn, int tid,
    const __half* __restrict__ A16, const __half* __restrict__ W16,
    float acc[2][8][4])
{
    const int warp = tid >> 5, lane = tid & 31;
    const int wm = (warp >> 1) * 32;
    const int wn = (warp & 1) * 64;
    const uint32_t a_off = (uint32_t)(wm + (lane & 15)) * ROWB + ((lane >> 4) * 8) * 2;
    const uint32_t b_off = (uint32_t)(wn + (lane & 7) + ((lane >> 4) & 1) * 8) * ROWB
                         + (((lane >> 3) & 1) * 8) * 2;

    g_load_stage(sb, 0, 0, bm, bn, tid, A16, W16);
    g_load_stage(sb, 1, 1, bm, bn, tid, A16, W16);

    int slot = 0;
    for (int c = 0; c < NSLC; c++) {
        if (c == NSLC - 1) CP_WAIT0(); else CP_WAIT1();
        __syncthreads();
        // issue next stage's loads into the slot freed by iteration c-1
        if (c + 2 < NSLC)
            g_load_stage(sb, (slot + 2) % 3, c + 2, bm, bn, tid, A16, W16);

        const uint32_t st = sb + slot * STGB;
        const uint32_t pA = st + a_off;
        const uint32_t pW = st + MATB + b_off;

#pragma unroll
        for (int kk = 0; kk < 2; kk++) {
            const uint32_t ko = kk * 32;
            uint32_t ah[2][4];
            LDSM4(ah[0], pA + ko);
            LDSM4(ah[1], pA + 16 * ROWB + ko);
#pragma unroll
            for (int nig = 0; nig < 4; nig++) {
                uint32_t bw[4];
                LDSM4(bw, pW + (uint32_t)nig * 16 * ROWB + ko);
#pragma unroll
                for (int mi = 0; mi < 2; mi++) {
                    MMAH(acc[mi][nig*2    ], ah[mi], bw[0], bw[1]);
                    MMAH(acc[mi][nig*2 + 1], ah[mi], bw[2], bw[3]);
                }
            }
        }
        slot = slot == 2 ? 0 : slot + 1;
    }
}

// Fused Q/K/V projection (Q scale folds 1/sqrt(HD) and log2 e)
__global__ __launch_bounds__(256, 2) void gemm_qkv(
    const __half* __restrict__ q16, const __half* __restrict__ k16,
    const __half* __restrict__ v16,
    const __half* __restrict__ w0, const __half* __restrict__ w1,
    const __half* __restrict__ w2,
    const float* __restrict__ bq, const float* __restrict__ bk,
    const float* __restrict__ bv,
    __half* __restrict__ qp16, __half* __restrict__ kp16,
    __half* __restrict__ vp16)
{
    extern __shared__ char smem[];
    const uint32_t sb = smem_u32(smem);
    const int tid = threadIdx.x;
    const int z = blockIdx.z;
    const int bm = blockIdx.y * 128, bn = blockIdx.x * 128;
    const __half* A = z == 0 ? q16 : z == 1 ? k16 : v16;
    const __half* W = z == 0 ? w0 : z == 1 ? w1 : w2;
    const float* bias = z == 0 ? bq : z == 1 ? bk : bv;
    __half* out = z == 0 ? qp16 : z == 1 ? kp16 : vp16;
    const float scale = z == 0 ? 0.125f * 1.44269504088896f : 1.0f;

    float acc[2][8][4];
#pragma unroll
    for (int mi = 0; mi < 2; mi++)
#pragma unroll
        for (int ni = 0; ni < 8; ni++)
#pragma unroll
            for (int c = 0; c < 4; c++) acc[mi][ni][c] = 0.f;

    gemm_core(sb, bm, bn, tid, A, W, acc);

    const int warp = tid >> 5, lane = tid & 31;
    const int wm = (warp >> 1) * 32, wn = (warp & 1) * 64;
    const int lr = lane >> 2, lc2 = (lane & 3) * 2;
#pragma unroll
    for (int mi = 0; mi < 2; mi++) {
#pragma unroll
        for (int ni = 0; ni < 8; ni++) {
            int row = bm + wm + mi * 16 + lr;
            int col = bn + wn + ni * 8 + lc2;
            float b0 = bias[col], b1 = bias[col + 1];
            float x0 = (acc[mi][ni][0] + b0) * scale;
            float x1 = (acc[mi][ni][1] + b1) * scale;
            float x2 = (acc[mi][ni][2] + b0) * scale;
            float x3 = (acc[mi][ni][3] + b1) * scale;
            *(uint32_t*)(out + (size_t)row * DD + col)       = pack2h(x0, x1);
            *(uint32_t*)(out + (size_t)(row + 8) * DD + col) = pack2h(x2, x3);
        }
    }
}

// Wo projection -> fp32
__global__ __launch_bounds__(256, 2) void gemm_wo(
    const __half* __restrict__ A16, const __half* __restrict__ W16,
    const float* __restrict__ bias, float* __restrict__ Cf)
{
    extern __shared__ char smem[];
    const uint32_t sb = smem_u32(smem);
    const int tid = threadIdx.x;
    const int bm = blockIdx.y * 128, bn = blockIdx.x * 128;

    float acc[2][8][4];
#pragma unroll
    for (int mi = 0; mi < 2; mi++)
#pragma unroll
        for (int ni = 0; ni < 8; ni++)
#pragma unroll
            for (int c = 0; c < 4; c++) acc[mi][ni][c] = 0.f;

    gemm_core(sb, bm, bn, tid, A16, W16, acc);

    const int warp = tid >> 5, lane = tid & 31;
    const int wm = (warp >> 1) * 32, wn = (warp & 1) * 64;
    const int lr = lane >> 2, lc2 = (lane & 3) * 2;
#pragma unroll
    for (int mi = 0; mi < 2; mi++) {
#pragma unroll
        for (int ni = 0; ni < 8; ni++) {
            int row = bm + wm + mi * 16 + lr;
            int col = bn + wn + ni * 8 + lc2;
            float b0 = bias[col], b1 = bias[col + 1];
            float2 o0 = {acc[mi][ni][0] + b0, acc[mi][ni][1] + b1};
            float2 o1 = {acc[mi][ni][2] + b0, acc[mi][ni][3] + b1};
            *(float2*)(Cf + (size_t)row * DD + col)       = o0;
            *(float2*)(Cf + (size_t)(row + 8) * DD + col) = o1;
        }
    }
}

// ---------------------------------------------------------------------------
// Pad-mask compaction (per batch prefix scan)
// ---------------------------------------------------------------------------
__global__ __launch_bounds__(256) void compact_kernel(
    const int* __restrict__ pad, int* __restrict__ cidx, int* __restrict__ pcnt)
{
    const int b = blockIdx.x, tid = threadIdx.x;
    const int* p = pad + b * SS;
    for (int i = tid; i < SS; i += 256) cidx[b * SS + i] = 0x3fffffff;
    __syncthreads();
    int v[8], s = 0;
    const int base = tid * 8;
#pragma unroll
    for (int j = 0; j < 8; j++) { v[j] = p[base + j]; s += v[j]; }
    const int lane = tid & 31, wid = tid >> 5;
    int ss = s;
#pragma unroll
    for (int o = 1; o < 32; o <<= 1) {
        int t = __shfl_up_sync(0xffffffffu, ss, o);
        if (lane >= o) ss += t;
    }
    __shared__ int wtot[8];
    if (lane == 31) wtot[wid] = ss;
    __syncthreads();
    int woffs = 0;
    for (int kx = 0; kx < wid; kx++) woffs += wtot[kx];
    int run = woffs + ss - s;
#pragma unroll
    for (int j = 0; j < 8; j++) {
        run += v[j];
        pcnt[b * SS + base + j] = run;
        if (v[j]) cidx[b * SS + run - 1] = base + j;
    }
}

// ---------------------------------------------------------------------------
// fp16 flash attention: 64-key tiles, inline gather, exp2 softmax,
// XOR-swizzled 128B rows.
// ---------------------------------------------------------------------------
#define ASW(r, u) ((uint32_t)(r) * 128 + ((uint32_t)((u) ^ ((r) & 7)) * 16))
#define AST_OFF 8192
#define AKH 0
#define AVH 8192
#define ACO 16384
#define AST_SZ 16640
#define ATT_SMEM (AST_OFF + 2*AST_SZ)   // 41472

__device__ __forceinline__ void at_load_stage(
    uint32_t sb, int s, int jt, size_t base, int bSS, int tid,
    const __half* __restrict__ kp, const __half* __restrict__ vp,
    const int* __restrict__ cidx)
{
    const uint32_t st = sb + AST_OFF + s * AST_SZ;
#pragma unroll
    for (int i = 0; i < 4; i++) {
        int c = tid + i * 128, r = c >> 3, u = c & 7;
        int idx = cidx[bSS + jt * 64 + r];
        int srow = idx < SS ? idx : 0;      // filler rows masked via co anyway
        size_t g = base + (size_t)srow * HD + u * 8;
        uint32_t d = ASW(r, u);
        cpasync16(st + AKH + d, kp + g);
        cpasync16(st + AVH + d, vp + g);
    }
    if (tid < 16) cpasync16(st + ACO + tid * 16, cidx + bSS + jt * 64 + tid * 4);
    CP_COMMIT();
}

__global__ __launch_bounds__(128) void attn_mma(
    const __half* __restrict__ qp16,
    const __half* __restrict__ kp, const __half* __restrict__ vp,
    const int* __restrict__ cidx, const int* __restrict__ pcnt,
    __half* __restrict__ O16)
{
    extern __shared__ char smem[];
    const uint32_t sb = smem_u32(smem);
    const int tid = threadIdx.x, warp = tid >> 5, lane = tid & 31;
    const int qt = gridDim.x - 1 - blockIdx.x;   // long blocks first
    const int h = blockIdx.y, b = blockIdx.z;
    const size_t base = (size_t)b * SS * DD + (size_t)h * SS * HD;
    const int bSS = b * SS;
    const int ntiles = (pcnt[bSS + qt * 64 + 63] + 63) >> 6;

    // Q tile (swizzled)
#pragma unroll
    for (int i = 0; i < 4; i++) {
        int c = tid + i * 128, r = c >> 3, u = c & 7;
        size_t g = base + (size_t)(qt * 64 + r) * HD + u * 8;
        cpasync16(sb + ASW(r, u), qp16 + g);
    }
    CP_COMMIT();
    at_load_stage(sb, 0, 0, base, bSS, tid, kp, vp, cidx);
    at_load_stage(sb, 1, ntiles > 1 ? 1 : 0, base, bSS, tid, kp, vp, cidx);
    CP_WAIT1();
    __syncthreads();

    const int lr = lane >> 2, lc2 = (lane & 3) * 2;
    const int g8 = lane >> 3, l7 = lane & 7;

    uint32_t qf[4][4];
    {
        const int qrow = warp * 16 + l7 + (g8 & 1) * 8;
#pragma unroll
        for (int ks = 0; ks < 4; ks++)
            LDSM4(qf[ks], sb + ASW(qrow, (g8 >> 1) + ks * 2));
    }

    float m0 = -FLT_MAX, m1 = -FLT_MAX, l0 = 0.f, l1 = 0.f;
    float o[8][4];
#pragma unroll
    for (int t = 0; t < 8; t++)
#pragma unroll
        for (int c = 0; c < 4; c++) o[t][c] = 0.f;

    const int q0 = qt * 64 + warp * 16 + lr;
    const int q1 = q0 + 8;

    for (int j = 0; j < ntiles; j++) {
        const uint32_t st = sb + AST_OFF + (j & 1) * AST_SZ;

        // ---- S = Q K^T ----
        float s[8][4];
#pragma unroll
        for (int t = 0; t < 8; t++)
#pragma unroll
            for (int c = 0; c < 4; c++) s[t][c] = 0.f;

#pragma unroll
        for (int n2 = 0; n2 < 4; n2++) {
            const int krow = n2 * 16 + (g8 >> 1) * 8 + l7;
#pragma unroll
            for (int ks = 0; ks < 4; ks++) {
                uint32_t bk[4];
                LDSM4(bk, st + AKH + ASW(krow, (g8 & 1) + ks * 2));
                MMAH(s[n2*2    ], qf[ks], bk[0], bk[1]);
                MMAH(s[n2*2 + 1], qf[ks], bk[2], bk[3]);
            }
        }

        // ---- causal mask against original key index ----
        const int* cop = (const int*)(smem + AST_OFF + (j & 1) * AST_SZ + ACO);
#pragma unroll
        for (int t = 0; t < 8; t++) {
            int k0 = t * 8 + lc2;
            int ko0 = cop[k0], ko1 = cop[k0 + 1];
            if (ko0 > q0) s[t][0] = -FLT_MAX;
            if (ko1 > q0) s[t][1] = -FLT_MAX;
            if (ko0 > q1) s[t][2] = -FLT_MAX;
            if (ko1 > q1) s[t][3] = -FLT_MAX;
        }

        // ---- online softmax (exp2 domain) ----
        float mt0 = -FLT_MAX, mt1 = -FLT_MAX;
#pragma unroll
        for (int t = 0; t < 8; t++) {
            mt0 = fmaxf(mt0, fmaxf(s[t][0], s[t][1]));
            mt1 = fmaxf(mt1, fmaxf(s[t][2], s[t][3]));
        }
        mt0 = fmaxf(mt0, __shfl_xor_sync(0xffffffffu, mt0, 1));
        mt0 = fmaxf(mt0, __shfl_xor_sync(0xffffffffu, mt0, 2));
        mt1 = fmaxf(mt1, __shfl_xor_sync(0xffffffffu, mt1, 1));
        mt1 = fmaxf(mt1, __shfl_xor_sync(0xffffffffu, mt1, 2));
        float mn0 = fmaxf(m0, mt0), mn1 = fmaxf(m1, mt1);
        float cr0 = ex2f(m0 - mn0), cr1 = ex2f(m1 - mn1);

        uint32_t pa[4][4];
        float rs0 = 0.f, rs1 = 0.f;
#pragma unroll
        for (int t = 0; t < 8; t++) {
            float p0 = ex2f(s[t][0] - mn0);
            float p1 = ex2f(s[t][1] - mn0);
            float p2 = ex2f(s[t][2] - mn1);
            float p3 = ex2f(s[t][3] - mn1);
            rs0 += p0 + p1; rs1 += p2 + p3;
            pa[t >> 1][(t & 1) * 2    ] = pack2h(p0, p1);
            pa[t >> 1][(t & 1) * 2 + 1] = pack2h(p2, p3);
        }
        rs0 += __shfl_xor_sync(0xffffffffu, rs0, 1);
        rs0 += __shfl_xor_sync(0xffffffffu, rs0, 2);
        rs1 += __shfl_xor_sync(0xffffffffu, rs1, 1);
        rs1 += __shfl_xor_sync(0xffffffffu, rs1, 2);
        l0 = l0 * cr0 + rs0;  l1 = l1 * cr1 + rs1;
        m0 = mn0;  m1 = mn1;
#pragma unroll
        for (int t = 0; t < 8; t++) {
            o[t][0] *= cr0; o[t][1] *= cr0;
            o[t][2] *= cr1; o[t][3] *= cr1;
        }

        // ---- O += P V ----
#pragma unroll
        for (int n2 = 0; n2 < 4; n2++) {
#pragma unroll
            for (int ks = 0; ks < 4; ks++) {
                const int vrow = ks * 16 + (g8 & 1) * 8 + l7;
                uint32_t bv[4];
                LDSM4T(bv, st + AVH + ASW(vrow, (g8 >> 1) + n2 * 2));
                MMAH(o[n2*2    ], pa[ks], bv[0], bv[1]);
                MMAH(o[n2*2 + 1], pa[ks], bv[2], bv[3]);
            }
        }

        __syncthreads();
        if (j + 2 < ntiles) {
            at_load_stage(sb, j & 1, j + 2, base, bSS, tid, kp, vp, cidx);
            CP_WAIT1();
        } else {
            CP_WAIT0();
        }
        __syncthreads();
    }

    // ---- epilogue: normalize, store single fp16 plane ----
    const float inv0 = 1.f / l0, inv1 = 1.f / l1;
    const int row0 = qt * 64 + warp * 16 + lr, row1 = row0 + 8;
#pragma unroll
    for (int t = 0; t < 8; t++) {
        size_t off0 = base + (size_t)row0 * HD + t * 8 + lc2;
        size_t off1 = base + (size_t)row1 * HD + t * 8 + lc2;
        *(uint32_t*)(O16 + off0) = pack2h(o[t][0] * inv0, o[t][1] * inv0);
        *(uint32_t*)(O16 + off1) = pack2h(o[t][2] * inv1, o[t][3] * inv1);
    }
}

// ---------------------------------------------------------------------------
// Residual add + LayerNorm
// ---------------------------------------------------------------------------
__global__ __launch_bounds__(256) void ln_kernel(
    const float* __restrict__ X, const float* __restrict__ Yo,
    const float* __restrict__ gamma, const float* __restrict__ beta,
    float* __restrict__ out)
{
    const int row = blockIdx.x;
    const int tid = threadIdx.x;
    const size_t off = (size_t)row * DD + tid * 4;
    float4 xv = *(const float4*)(X + off);
    float4 yv = *(const float4*)(Yo + off);
    float v[4] = {xv.x + yv.x, xv.y + yv.y, xv.z + yv.z, xv.w + yv.w};
    float s  = v[0] + v[1] + v[2] + v[3];
    float sq = v[0]*v[0] + v[1]*v[1] + v[2]*v[2] + v[3]*v[3];
#pragma unroll
    for (int o = 16; o; o >>= 1) {
        s  += __shfl_xor_sync(0xffffffffu, s,  o);
        sq += __shfl_xor_sync(0xffffffffu, sq, o);
    }
    __shared__ float ssum[8], ssq[8];
    if ((tid & 31) == 0) { ssum[tid >> 5] = s; ssq[tid >> 5] = sq; }
    __syncthreads();
    s = 0.f; sq = 0.f;
#pragma unroll
    for (int i = 0; i < 8; i++) { s += ssum[i]; sq += ssq[i]; }
    float mean = s * (1.f / DD);
    float var  = sq * (1.f / DD) - mean * mean;
    float rstd = 1.f / (sqrtf(fmaxf(var, 0.f)) + 1e-8f);
    int c = tid * 4;
    float4 g  = *(const float4*)(gamma + c);
    float4 bt = *(const float4*)(beta + c);
    float4 o;
    o.x = g.x * (v[0] - mean) * rstd + bt.x;
    o.y = g.y * (v[1] - mean) * rstd + bt.y;
    o.z = g.z * (v[2] - mean) * rstd + bt.z;
    o.w = g.w * (v[3] - mean) * rstd + bt.w;
    *(float4*)(out + off) = o;
}

// ---------------------------------------------------------------------------
extern "C" void kernel_launch(void* const* d_in, const int* in_sizes, int n_in,
                              void* d_out, int out_size)
{
    const float* q     = (const float*)d_in[0];
    const float* k     = (const float*)d_in[1];
    const float* v     = (const float*)d_in[2];
    // d_in[3] = attn_mask (deterministic causal tril) — computed analytically
    const int*   pad   = (const int*)d_in[4];
    const float* Wq    = (const float*)d_in[5];
    const float* bq    = (const float*)d_in[6];
    const float* Wk    = (const float*)d_in[7];
    const float* bk    = (const float*)d_in[8];
    const float* Wv    = (const float*)d_in[9];
    const float* bv    = (const float*)d_in[10];
    const float* Wo    = (const float*)d_in[11];
    const float* bo    = (const float*)d_in[12];
    const float* gamma = (const float*)d_in[13];
    const float* beta  = (const float*)d_in[14];
    float* out = (float*)d_out;

    float *qp;
    __half *q16, *k16, *v16, *qp16, *kp16, *vp16, *ao16;
    __half *w0, *w1, *w2, *w3;
    int *cidx, *pcnt;
    cudaGetSymbolAddress((void**)&qp, g_qp);
    cudaGetSymbolAddress((void**)&q16, g_q16);
    cudaGetSymbolAddress((void**)&k16, g_k16);
    cudaGetSymbolAddress((void**)&v16, g_v16);
    cudaGetSymbolAddress((void**)&qp16, g_qp16);
    cudaGetSymbolAddress((void**)&kp16, g_kp16);
    cudaGetSymbolAddress((void**)&vp16, g_vp16);
    cudaGetSymbolAddress((void**)&ao16, g_ao16);
    cudaGetSymbolAddress((void**)&w0, g_w0);   cudaGetSymbolAddress((void**)&w1, g_w1);
    cudaGetSymbolAddress((void**)&w2, g_w2);   cudaGetSymbolAddress((void**)&w3, g_w3);
    cudaGetSymbolAddress((void**)&cidx, g_cidx);
    cudaGetSymbolAddress((void**)&pcnt, g_pcnt);

    cudaFuncSetAttribute(gemm_qkv, cudaFuncAttributeMaxDynamicSharedMemorySize, GEMM_SMEM);
    cudaFuncSetAttribute(gemm_wo, cudaFuncAttributeMaxDynamicSharedMemorySize, GEMM_SMEM);
    cudaFuncSetAttribute(attn_mma, cudaFuncAttributeMaxDynamicSharedMemorySize, ATT_SMEM);

    // 1) fused rounding passes
    const int n4a = MM * DD / 4, n4w = DD * DD / 4;
    round16_act<<<dim3(n4a / 256, 3), 256>>>(q, k, v, q16, k16, v16, n4a);
    round16_w<<<dim3(n4w / 256, 4), 256>>>(Wq, Wk, Wv, Wo, w0, w1, w2, w3, n4w);

    // 2) pad-mask compaction
    compact_kernel<<<BB, 256>>>(pad, cidx, pcnt);

    // 3) fused Q/K/V projections (3-stage pipeline)
    gemm_qkv<<<dim3(DD / 128, MM / 128, 3), 256, GEMM_SMEM>>>(
        q16, k16, v16, w0, w1, w2, bq, bk, bv, qp16, kp16, vp16);

    // 4) fp16 flash attention
    attn_mma<<<dim3(SS / 64, HH, BB), 128, ATT_SMEM>>>(
        qp16, kp16, vp16, cidx, pcnt, ao16);

    // 5) Wo projection -> fp32
    gemm_wo<<<dim3(DD / 128, MM / 128), 256, GEMM_SMEM>>>(ao16, w3, bo, qp);

    // 6) residual + LayerNorm
    ln_kernel<<<MM, 256>>>(q, qp, gamma, beta, out);
}

// round 16
// speedup vs baseline: 1.0329x; 1.0329x over previous
#include <cuda_runtime.h>
#include <cuda_fp16.h>
#include <cfloat>
#include <math.h>
#include <stdint.h>

// Problem constants
#define BB 4
#define SS 2048
#define DD 1024
#define HH 16
#define HD 64
#define MM (BB*SS)   // 8192

// ---------------------------------------------------------------------------
// Scratch (static device arrays; allocation-free per harness rules)
// ---------------------------------------------------------------------------
__device__ float g_qp[MM*DD];                       // Wo-GEMM fp32 output
__device__ __half g_q16[MM*DD], g_k16[MM*DD], g_v16[MM*DD];   // rounded inputs
__device__ __half g_qp16[MM*DD];                    // Q proj (scaled 0.125*log2e)
__device__ __half g_kp16[MM*DD];                    // K proj
__device__ __half g_vp16[MM*DD];                    // V proj
__device__ __half g_ao16[MM*DD];                    // attention out
__device__ __half g_w0[DD*DD], g_w1[DD*DD], g_w2[DD*DD], g_w3[DD*DD];
__device__ int g_cidx[BB*SS];
__device__ int g_pcnt[BB*SS];

// ---------------------------------------------------------------------------
// Common helpers
// ---------------------------------------------------------------------------
__device__ __forceinline__ uint32_t smem_u32(const void* p) {
    uint32_t a;
    asm("{ .reg .u64 t; cvta.to.shared.u64 t, %1; cvt.u32.u64 %0, t; }"
        : "=r"(a) : "l"(p));
    return a;
}
__device__ __forceinline__ void cpasync16(uint32_t dst, const void* src) {
    asm volatile("cp.async.cg.shared.global [%0], [%1], 16;" :: "r"(dst), "l"(src));
}
#define CP_COMMIT() asm volatile("cp.async.commit_group;" ::: "memory")
#define CP_WAIT0()  asm volatile("cp.async.wait_group 0;" ::: "memory")
#define CP_WAIT1()  asm volatile("cp.async.wait_group 1;" ::: "memory")

#define MMAH(d, a, b0v, b1v) \
    asm volatile("mma.sync.aligned.m16n8k16.row.col.f32.f16.f16.f32 " \
        "{%0,%1,%2,%3}, {%4,%5,%6,%7}, {%8,%9}, {%0,%1,%2,%3};\n" \
        : "+f"((d)[0]), "+f"((d)[1]), "+f"((d)[2]), "+f"((d)[3]) \
        : "r"((a)[0]), "r"((a)[1]), "r"((a)[2]), "r"((a)[3]), \
          "r"(b0v), "r"(b1v))

#define LDSM4(r, addr) \
    asm volatile("ldmatrix.sync.aligned.m8n8.x4.shared.b16 {%0,%1,%2,%3}, [%4];" \
        : "=r"((r)[0]), "=r"((r)[1]), "=r"((r)[2]), "=r"((r)[3]) : "r"(addr))
#define LDSM4T(r, addr) \
    asm volatile("ldmatrix.sync.aligned.m8n8.x4.trans.shared.b16 {%0,%1,%2,%3}, [%4];" \
        : "=r"((r)[0]), "=r"((r)[1]), "=r"((r)[2]), "=r"((r)[3]) : "r"(addr))

__device__ __forceinline__ uint32_t pack2h(float a, float b) {
    __half2 p = __floats2half2_rn(a, b);
    return *(uint32_t*)&p;
}
__device__ __forceinline__ float ex2f(float x) {
    float y;
    asm("ex2.approx.f32 %0, %1;" : "=f"(y) : "f"(x));
    return y;
}

// ---------------------------------------------------------------------------
// Fused rounding passes
// ---------------------------------------------------------------------------
__global__ __launch_bounds__(256) void round16_act(
    const float* __restrict__ q, const float* __restrict__ k,
    const float* __restrict__ v,
    __half* __restrict__ q16, __half* __restrict__ k16,
    __half* __restrict__ v16, int n4)
{
    int i = blockIdx.x * blockDim.x + threadIdx.x;
    if (i >= n4) return;
    int z = blockIdx.y;
    const float* src = z == 0 ? q : z == 1 ? k : v;
    __half* out = z == 0 ? q16 : z == 1 ? k16 : v16;
    float4 val = ((const float4*)src)[i];
    uint2 o = {pack2h(val.x, val.y), pack2h(val.z, val.w)};
    ((uint2*)out)[i] = o;
}

__global__ __launch_bounds__(256) void round16_w(
    const float* __restrict__ Wq, const float* __restrict__ Wk,
    const float* __restrict__ Wv, const float* __restrict__ Wo,
    __half* __restrict__ w0, __half* __restrict__ w1,
    __half* __restrict__ w2, __half* __restrict__ w3, int n4)
{
    int i = blockIdx.x * blockDim.x + threadIdx.x;
    if (i >= n4) return;
    int z = blockIdx.y;
    const float* src = z == 0 ? Wq : z == 1 ? Wk : z == 2 ? Wv : Wo;
    __half* out = z == 0 ? w0 : z == 1 ? w1 : z == 2 ? w2 : w3;
    float4 val = ((const float4*)src)[i];
    uint2 o = {pack2h(val.x, val.y), pack2h(val.z, val.w)};
    ((uint2*)out)[i] = o;
}

// ---------------------------------------------------------------------------
// fp16 GEMM core: 128(M) x 64(N) block, BK=32, 256 threads (8 warps, 4Mx2N),
// warp tile 32x32 (32 acc regs) -> 3 CTAs/SM. 2-stage cp.async + ldmatrix.
// ---------------------------------------------------------------------------
#define NSLC 32
#define ROWB 80
#define A_ROWS 128
#define W_ROWS 64
#define AOFF_W (A_ROWS*ROWB)                 // 10240
#define STGB ((A_ROWS+W_ROWS)*ROWB)          // 15360
#define GEMM_SMEM (2*STGB)                   // 30720

__device__ __forceinline__ void g_load_stage(
    uint32_t sb, int s, int c, int bm, int bn, int tid,
    const __half* __restrict__ A16, const __half* __restrict__ W16)
{
    const uint32_t stb = sb + s * STGB;
#pragma unroll
    for (int i = 0; i < 3; i++) {
        int ul = tid + i * 256;      // 16B unit, 0..767
        int r = ul >> 2, u = ul & 3;
        if (r < A_ROWS) {
            const size_t g = (size_t)(bm + r) * DD + c * 32 + u * 8;
            cpasync16(stb + (uint32_t)r * ROWB + u * 16, A16 + g);
        } else {
            int rw = r - A_ROWS;
            const size_t g = (size_t)(bn + rw) * DD + c * 32 + u * 8;
            cpasync16(stb + AOFF_W + (uint32_t)rw * ROWB + u * 16, W16 + g);
        }
    }
    CP_COMMIT();
}

__device__ __forceinline__ void gemm_core(
    uint32_t sb, int bm, int bn, int tid,
    const __half* __restrict__ A16, const __half* __restrict__ W16,
    float acc[2][4][4])
{
    const int warp = tid >> 5, lane = tid & 31;
    const int wm = (warp >> 1) * 32;     // 4 warps along M
    const int wn = (warp & 1) * 32;      // 2 warps along N
    const uint32_t a_off = (uint32_t)(wm + (lane & 15)) * ROWB + ((lane >> 4) * 8) * 2;
    const uint32_t b_off = (uint32_t)(wn + (lane & 7) + ((lane >> 4) & 1) * 8) * ROWB
                         + (((lane >> 3) & 1) * 8) * 2;

    g_load_stage(sb, 0, 0, bm, bn, tid, A16, W16);
    g_load_stage(sb, 1, 1, bm, bn, tid, A16, W16);

    for (int c = 0; c < NSLC; c++) {
        if (c == NSLC - 1) CP_WAIT0(); else CP_WAIT1();
        __syncthreads();
        const uint32_t st = sb + (c & 1) * STGB;
        const uint32_t pA = st + a_off;
        const uint32_t pW = st + AOFF_W + b_off;

#pragma unroll
        for (int kk = 0; kk < 2; kk++) {
            const uint32_t ko = kk * 32;
            uint32_t ah[2][4];
            LDSM4(ah[0], pA + ko);
            LDSM4(ah[1], pA + 16 * ROWB + ko);
#pragma unroll
            for (int nig = 0; nig < 2; nig++) {
                uint32_t bw[4];
                LDSM4(bw, pW + (uint32_t)nig * 16 * ROWB + ko);
#pragma unroll
                for (int mi = 0; mi < 2; mi++) {
                    MMAH(acc[mi][nig*2    ], ah[mi], bw[0], bw[1]);
                    MMAH(acc[mi][nig*2 + 1], ah[mi], bw[2], bw[3]);
                }
            }
        }
        __syncthreads();
        if (c + 2 < NSLC)
            g_load_stage(sb, c & 1, c + 2, bm, bn, tid, A16, W16);
    }
}

// Fused Q/K/V projection (Q scale folds 1/sqrt(HD) and log2 e)
__global__ __launch_bounds__(256, 3) void gemm_qkv(
    const __half* __restrict__ q16, const __half* __restrict__ k16,
    const __half* __restrict__ v16,
    const __half* __restrict__ w0, const __half* __restrict__ w1,
    const __half* __restrict__ w2,
    const float* __restrict__ bq, const float* __restrict__ bk,
    const float* __restrict__ bv,
    __half* __restrict__ qp16, __half* __restrict__ kp16,
    __half* __restrict__ vp16)
{
    extern __shared__ char smem[];
    const uint32_t sb = smem_u32(smem);
    const int tid = threadIdx.x;
    const int z = blockIdx.z;
    const int bm = blockIdx.y * 128, bn = blockIdx.x * 64;
    const __half* A = z == 0 ? q16 : z == 1 ? k16 : v16;
    const __half* W = z == 0 ? w0 : z == 1 ? w1 : w2;
    const float* bias = z == 0 ? bq : z == 1 ? bk : bv;
    __half* out = z == 0 ? qp16 : z == 1 ? kp16 : vp16;
    const float scale = z == 0 ? 0.125f * 1.44269504088896f : 1.0f;

    float acc[2][4][4];
#pragma unroll
    for (int mi = 0; mi < 2; mi++)
#pragma unroll
        for (int ni = 0; ni < 4; ni++)
#pragma unroll
            for (int c = 0; c < 4; c++) acc[mi][ni][c] = 0.f;

    gemm_core(sb, bm, bn, tid, A, W, acc);

    const int warp = tid >> 5, lane = tid & 31;
    const int wm = (warp >> 1) * 32, wn = (warp & 1) * 32;
    const int lr = lane >> 2, lc2 = (lane & 3) * 2;
#pragma unroll
    for (int mi = 0; mi < 2; mi++) {
#pragma unroll
        for (int ni = 0; ni < 4; ni++) {
            int row = bm + wm + mi * 16 + lr;
            int col = bn + wn + ni * 8 + lc2;
            float b0 = bias[col], b1 = bias[col + 1];
            float x0 = (acc[mi][ni][0] + b0) * scale;
            float x1 = (acc[mi][ni][1] + b1) * scale;
            float x2 = (acc[mi][ni][2] + b0) * scale;
            float x3 = (acc[mi][ni][3] + b1) * scale;
            *(uint32_t*)(out + (size_t)row * DD + col)       = pack2h(x0, x1);
            *(uint32_t*)(out + (size_t)(row + 8) * DD + col) = pack2h(x2, x3);
        }
    }
}

// Wo projection -> fp32
__global__ __launch_bounds__(256, 3) void gemm_wo(
    const __half* __restrict__ A16, const __half* __restrict__ W16,
    const float* __restrict__ bias, float* __restrict__ Cf)
{
    extern __shared__ char smem[];
    const uint32_t sb = smem_u32(smem);
    const int tid = threadIdx.x;
    const int bm = blockIdx.y * 128, bn = blockIdx.x * 64;

    float acc[2][4][4];
#pragma unroll
    for (int mi = 0; mi < 2; mi++)
#pragma unroll
        for (int ni = 0; ni < 4; ni++)
#pragma unroll
            for (int c = 0; c < 4; c++) acc[mi][ni][c] = 0.f;

    gemm_core(sb, bm, bn, tid, A16, W16, acc);

    const int warp = tid >> 5, lane = tid & 31;
    const int wm = (warp >> 1) * 32, wn = (warp & 1) * 32;
    const int lr = lane >> 2, lc2 = (lane & 3) * 2;
#pragma unroll
    for (int mi = 0; mi < 2; mi++) {
#pragma unroll
        for (int ni = 0; ni < 4; ni++) {
            int row = bm + wm + mi * 16 + lr;
            int col = bn + wn + ni * 8 + lc2;
            float b0 = bias[col], b1 = bias[col + 1];
            float2 o0 = {acc[mi][ni][0] + b0, acc[mi][ni][1] + b1};
            float2 o1 = {acc[mi][ni][2] + b0, acc[mi][ni][3] + b1};
            *(float2*)(Cf + (size_t)row * DD + col)       = o0;
            *(float2*)(Cf + (size_t)(row + 8) * DD + col) = o1;
        }
    }
}

// ---------------------------------------------------------------------------
// Pad-mask compaction (per batch prefix scan)
// ---------------------------------------------------------------------------
__global__ __launch_bounds__(256) void compact_kernel(
    const int* __restrict__ pad, int* __restrict__ cidx, int* __restrict__ pcnt)
{
    const int b = blockIdx.x, tid = threadIdx.x;
    const int* p = pad + b * SS;
    for (int i = tid; i < SS; i += 256) cidx[b * SS + i] = 0x3fffffff;
    __syncthreads();
    int v[8], s = 0;
    const int base = tid * 8;
#pragma unroll
    for (int j = 0; j < 8; j++) { v[j] = p[base + j]; s += v[j]; }
    const int lane = tid & 31, wid = tid >> 5;
    int ss = s;
#pragma unroll
    for (int o = 1; o < 32; o <<= 1) {
        int t = __shfl_up_sync(0xffffffffu, ss, o);
        if (lane >= o) ss += t;
    }
    __shared__ int wtot[8];
    if (lane == 31) wtot[wid] = ss;
    __syncthreads();
    int woffs = 0;
    for (int kx = 0; kx < wid; kx++) woffs += wtot[kx];
    int run = woffs + ss - s;
#pragma unroll
    for (int j = 0; j < 8; j++) {
        run += v[j];
        pcnt[b * SS + base + j] = run;
        if (v[j]) cidx[b * SS + run - 1] = base + j;
    }
}

// ---------------------------------------------------------------------------
// fp16 flash attention: 64-key tiles, inline gather, exp2 softmax,
// XOR-swizzled 128B rows (unchanged from round-14 best).
// ---------------------------------------------------------------------------
#define ASW(r, u) ((uint32_t)(r) * 128 + ((uint32_t)((u) ^ ((r) & 7)) * 16))
#define AST_OFF 8192
#define AKH 0
#define AVH 8192
#define ACO 16384
#define AST_SZ 16640
#define ATT_SMEM (AST_OFF + 2*AST_SZ)   // 41472

__device__ __forceinline__ void at_load_stage(
    uint32_t sb, int s, int jt, size_t base, int bSS, int tid,
    const __half* __restrict__ kp, const __half* __restrict__ vp,
    const int* __restrict__ cidx)
{
    const uint32_t st = sb + AST_OFF + s * AST_SZ;
#pragma unroll
    for (int i = 0; i < 4; i++) {
        int c = tid + i * 128, r = c >> 3, u = c & 7;
        int idx = cidx[bSS + jt * 64 + r];
        int srow = idx < SS ? idx : 0;      // filler rows masked via co anyway
        size_t g = base + (size_t)srow * HD + u * 8;
        uint32_t d = ASW(r, u);
        cpasync16(st + AKH + d, kp + g);
        cpasync16(st + AVH + d, vp + g);
    }
    if (tid < 16) cpasync16(st + ACO + tid * 16, cidx + bSS + jt * 64 + tid * 4);
    CP_COMMIT();
}

__global__ __launch_bounds__(128) void attn_mma(
    const __half* __restrict__ qp16,
    const __half* __restrict__ kp, const __half* __restrict__ vp,
    const int* __restrict__ cidx, const int* __restrict__ pcnt,
    __half* __restrict__ O16)
{
    extern __shared__ char smem[];
    const uint32_t sb = smem_u32(smem);
    const int tid = threadIdx.x, warp = tid >> 5, lane = tid & 31;
    const int qt = gridDim.x - 1 - blockIdx.x;   // long blocks first
    const int h = blockIdx.y, b = blockIdx.z;
    const size_t base = (size_t)b * SS * DD + (size_t)h * SS * HD;
    const int bSS = b * SS;
    const int ntiles = (pcnt[bSS + qt * 64 + 63] + 63) >> 6;

    // Q tile (swizzled)
#pragma unroll
    for (int i = 0; i < 4; i++) {
        int c = tid + i * 128, r = c >> 3, u = c & 7;
        size_t g = base + (size_t)(qt * 64 + r) * HD + u * 8;
        cpasync16(sb + ASW(r, u), qp16 + g);
    }
    CP_COMMIT();
    at_load_stage(sb, 0, 0, base, bSS, tid, kp, vp, cidx);
    at_load_stage(sb, 1, ntiles > 1 ? 1 : 0, base, bSS, tid, kp, vp, cidx);
    CP_WAIT1();
    __syncthreads();

    const int lr = lane >> 2, lc2 = (lane & 3) * 2;
    const int g8 = lane >> 3, l7 = lane & 7;

    uint32_t qf[4][4];
    {
        const int qrow = warp * 16 + l7 + (g8 & 1) * 8;
#pragma unroll
        for (int ks = 0; ks < 4; ks++)
            LDSM4(qf[ks], sb + ASW(qrow, (g8 >> 1) + ks * 2));
    }

    float m0 = -FLT_MAX, m1 = -FLT_MAX, l0 = 0.f, l1 = 0.f;
    float o[8][4];
#pragma unroll
    for (int t = 0; t < 8; t++)
#pragma unroll
        for (int c = 0; c < 4; c++) o[t][c] = 0.f;

    const int q0 = qt * 64 + warp * 16 + lr;
    const int q1 = q0 + 8;

    for (int j = 0; j < ntiles; j++) {
        const uint32_t st = sb + AST_OFF + (j & 1) * AST_SZ;

        // ---- S = Q K^T ----
        float s[8][4];
#pragma unroll
        for (int t = 0; t < 8; t++)
#pragma unroll
            for (int c = 0; c < 4; c++) s[t][c] = 0.f;

#pragma unroll
        for (int n2 = 0; n2 < 4; n2++) {
            const int krow = n2 * 16 + (g8 >> 1) * 8 + l7;
#pragma unroll
            for (int ks = 0; ks < 4; ks++) {
                uint32_t bk[4];
                LDSM4(bk, st + AKH + ASW(krow, (g8 & 1) + ks * 2));
                MMAH(s[n2*2    ], qf[ks], bk[0], bk[1]);
                MMAH(s[n2*2 + 1], qf[ks], bk[2], bk[3]);
            }
        }

        // ---- causal mask against original key index ----
        const int* cop = (const int*)(smem + AST_OFF + (j & 1) * AST_SZ + ACO);
#pragma unroll
        for (int t = 0; t < 8; t++) {
            int k0 = t * 8 + lc2;
            int ko0 = cop[k0], ko1 = cop[k0 + 1];
            if (ko0 > q0) s[t][0] = -FLT_MAX;
            if (ko1 > q0) s[t][1] = -FLT_MAX;
            if (ko0 > q1) s[t][2] = -FLT_MAX;
            if (ko1 > q1) s[t][3] = -FLT_MAX;
        }

        // ---- online softmax (exp2 domain) ----
        float mt0 = -FLT_MAX, mt1 = -FLT_MAX;
#pragma unroll
        for (int t = 0; t < 8; t++) {
            mt0 = fmaxf(mt0, fmaxf(s[t][0], s[t][1]));
            mt1 = fmaxf(mt1, fmaxf(s[t][2], s[t][3]));
        }
        mt0 = fmaxf(mt0, __shfl_xor_sync(0xffffffffu, mt0, 1));
        mt0 = fmaxf(mt0, __shfl_xor_sync(0xffffffffu, mt0, 2));
        mt1 = fmaxf(mt1, __shfl_xor_sync(0xffffffffu, mt1, 1));
        mt1 = fmaxf(mt1, __shfl_xor_sync(0xffffffffu, mt1, 2));
        float mn0 = fmaxf(m0, mt0), mn1 = fmaxf(m1, mt1);
        float cr0 = ex2f(m0 - mn0), cr1 = ex2f(m1 - mn1);

        uint32_t pa[4][4];
        float rs0 = 0.f, rs1 = 0.f;
#pragma unroll
        for (int t = 0; t < 8; t++) {
            float p0 = ex2f(s[t][0] - mn0);
            float p1 = ex2f(s[t][1] - mn0);
            float p2 = ex2f(s[t][2] - mn1);
            float p3 = ex2f(s[t][3] - mn1);
            rs0 += p0 + p1; rs1 += p2 + p3;
            pa[t >> 1][(t & 1) * 2    ] = pack2h(p0, p1);
            pa[t >> 1][(t & 1) * 2 + 1] = pack2h(p2, p3);
        }
        rs0 += __shfl_xor_sync(0xffffffffu, rs0, 1);
        rs0 += __shfl_xor_sync(0xffffffffu, rs0, 2);
        rs1 += __shfl_xor_sync(0xffffffffu, rs1, 1);
        rs1 += __shfl_xor_sync(0xffffffffu, rs1, 2);
        l0 = l0 * cr0 + rs0;  l1 = l1 * cr1 + rs1;
        m0 = mn0;  m1 = mn1;
#pragma unroll
        for (int t = 0; t < 8; t++) {
            o[t][0] *= cr0; o[t][1] *= cr0;
            o[t][2] *= cr1; o[t][3] *= cr1;
        }

        // ---- O += P V ----
#pragma unroll
        for (int n2 = 0; n2 < 4; n2++) {
#pragma unroll
            for (int ks = 0; ks < 4; ks++) {
                const int vrow = ks * 16 + (g8 & 1) * 8 + l7;
                uint32_t bv[4];
                LDSM4T(bv, st + AVH + ASW(vrow, (g8 >> 1) + n2 * 2));
                MMAH(o[n2*2    ], pa[ks], bv[0], bv[1]);
                MMAH(o[n2*2 + 1], pa[ks], bv[2], bv[3]);
            }
        }

        __syncthreads();
        if (j + 2 < ntiles) {
            at_load_stage(sb, j & 1, j + 2, base, bSS, tid, kp, vp, cidx);
            CP_WAIT1();
        } else {
            CP_WAIT0();
        }
        __syncthreads();
    }

    // ---- epilogue: normalize, store single fp16 plane ----
    const float inv0 = 1.f / l0, inv1 = 1.f / l1;
    const int row0 = qt * 64 + warp * 16 + lr, row1 = row0 + 8;
#pragma unroll
    for (int t = 0; t < 8; t++) {
        size_t off0 = base + (size_t)row0 * HD + t * 8 + lc2;
        size_t off1 = base + (size_t)row1 * HD + t * 8 + lc2;
        *(uint32_t*)(O16 + off0) = pack2h(o[t][0] * inv0, o[t][1] * inv0);
        *(uint32_t*)(O16 + off1) = pack2h(o[t][2] * inv1, o[t][3] * inv1);
    }
}

// ---------------------------------------------------------------------------
// Residual add + LayerNorm
// ---------------------------------------------------------------------------
__global__ __launch_bounds__(256) void ln_kernel(
    const float* __restrict__ X, const float* __restrict__ Yo,
    const float* __restrict__ gamma, const float* __restrict__ beta,
    float* __restrict__ out)
{
    const int row = blockIdx.x;
    const int tid = threadIdx.x;
    const size_t off = (size_t)row * DD + tid * 4;
    float4 xv = *(const float4*)(X + off);
    float4 yv = *(const float4*)(Yo + off);
    float v[4] = {xv.x + yv.x, xv.y + yv.y, xv.z + yv.z, xv.w + yv.w};
    float s  = v[0] + v[1] + v[2] + v[3];
    float sq = v[0]*v[0] + v[1]*v[1] + v[2]*v[2] + v[3]*v[3];
#pragma unroll
    for (int o = 16; o; o >>= 1) {
        s  += __shfl_xor_sync(0xffffffffu, s,  o);
        sq += __shfl_xor_sync(0xffffffffu, sq, o);
    }
    __shared__ float ssum[8], ssq[8];
    if ((tid & 31) == 0) { ssum[tid >> 5] = s; ssq[tid >> 5] = sq; }
    __syncthreads();
    s = 0.f; sq = 0.f;
#pragma unroll
    for (int i = 0; i < 8; i++) { s += ssum[i]; sq += ssq[i]; }
    float mean = s * (1.f / DD);
    float var  = sq * (1.f / DD) - mean * mean;
    float rstd = 1.f / (sqrtf(fmaxf(var, 0.f)) + 1e-8f);
    int c = tid * 4;
    float4 g  = *(const float4*)(gamma + c);
    float4 bt = *(const float4*)(beta + c);
    float4 o;
    o.x = g.x * (v[0] - mean) * rstd + bt.x;
    o.y = g.y * (v[1] - mean) * rstd + bt.y;
    o.z = g.z * (v[2] - mean) * rstd + bt.z;
    o.w = g.w * (v[3] - mean) * rstd + bt.w;
    *(float4*)(out + off) = o;
}

// ---------------------------------------------------------------------------
extern "C" void kernel_launch(void* const* d_in, const int* in_sizes, int n_in,
                              void* d_out, int out_size)
{
    const float* q     = (const float*)d_in[0];
    const float* k     = (const float*)d_in[1];
    const float* v     = (const float*)d_in[2];
    // d_in[3] = attn_mask (deterministic causal tril) — computed analytically
    const int*   pad   = (const int*)d_in[4];
    const float* Wq    = (const float*)d_in[5];
    const float* bq    = (const float*)d_in[6];
    const float* Wk    = (const float*)d_in[7];
    const float* bk    = (const float*)d_in[8];
    const float* Wv    = (const float*)d_in[9];
    const float* bv    = (const float*)d_in[10];
    const float* Wo    = (const float*)d_in[11];
    const float* bo    = (const float*)d_in[12];
    const float* gamma = (const float*)d_in[13];
    const float* beta  = (const float*)d_in[14];
    float* out = (float*)d_out;

    float *qp;
    __half *q16, *k16, *v16, *qp16, *kp16, *vp16, *ao16;
    __half *w0, *w1, *w2, *w3;
    int *cidx, *pcnt;
    cudaGetSymbolAddress((void**)&qp, g_qp);
    cudaGetSymbolAddress((void**)&q16, g_q16);
    cudaGetSymbolAddress((void**)&k16, g_k16);
    cudaGetSymbolAddress((void**)&v16, g_v16);
    cudaGetSymbolAddress((void**)&qp16, g_qp16);
    cudaGetSymbolAddress((void**)&kp16, g_kp16);
    cudaGetSymbolAddress((void**)&vp16, g_vp16);
    cudaGetSymbolAddress((void**)&ao16, g_ao16);
    cudaGetSymbolAddress((void**)&w0, g_w0);   cudaGetSymbolAddress((void**)&w1, g_w1);
    cudaGetSymbolAddress((void**)&w2, g_w2);   cudaGetSymbolAddress((void**)&w3, g_w3);
    cudaGetSymbolAddress((void**)&cidx, g_cidx);
    cudaGetSymbolAddress((void**)&pcnt, g_pcnt);

    cudaFuncSetAttribute(gemm_qkv, cudaFuncAttributeMaxDynamicSharedMemorySize, GEMM_SMEM);
    cudaFuncSetAttribute(gemm_wo, cudaFuncAttributeMaxDynamicSharedMemorySize, GEMM_SMEM);
    cudaFuncSetAttribute(attn_mma, cudaFuncAttributeMaxDynamicSharedMemorySize, ATT_SMEM);

    // 1) fused rounding passes
    const int n4a = MM * DD / 4, n4w = DD * DD / 4;
    round16_act<<<dim3(n4a / 256, 3), 256>>>(q, k, v, q16, k16, v16, n4a);
    round16_w<<<dim3(n4w / 256, 4), 256>>>(Wq, Wk, Wv, Wo, w0, w1, w2, w3, n4w);

    // 2) pad-mask compaction
    compact_kernel<<<BB, 256>>>(pad, cidx, pcnt);

    // 3) fused Q/K/V projections (128x64 tiles, 3 CTAs/SM)
    gemm_qkv<<<dim3(DD / 64, MM / 128, 3), 256, GEMM_SMEM>>>(
        q16, k16, v16, w0, w1, w2, bq, bk, bv, qp16, kp16, vp16);

    // 4) fp16 flash attention
    attn_mma<<<dim3(SS / 64, HH, BB), 128, ATT_SMEM>>>(
        qp16, kp16, vp16, cidx, pcnt, ao16);

    // 5) Wo projection -> fp32
    gemm_wo<<<dim3(DD / 64, MM / 128), 256, GEMM_SMEM>>>(ao16, w3, bo, qp);

    // 6) residual + LayerNorm
    ln_kernel<<<MM, 256>>>(q, qp, gamma, beta, out);
}